// round 9
// baseline (speedup 1.0000x reference)
#include <cuda_runtime.h>
#include <cuda_fp16.h>
#include <cstdint>

#define DB 4
#define DT 256
#define DU 64
#define DENC 512
#define DPRED 640
#define DJ 640
#define DV 1024
#define BT (DB*DT)        // 1024 enc rows
#define BUROWS (DB*DU)    // 256 pred rows
#define M_TOTAL (BT*DU)   // 65536 joint rows

// ---------------- device scratch (no allocations allowed) ----------------
__device__ float  g_encP[BT * DJ];                 // 2.6 MB
__device__ float  g_predP[BUROWS * DJ];            // 0.66 MB
__device__ __half g_Wh[DV * DJ];                   // W_out^T [v][k], fp16

// ---------------- tanh via MUFU.TANH --------------------------------------
__device__ __forceinline__ float tanha(float x) {
    float y;
    asm("tanh.approx.f32 %0, %1;" : "=f"(y) : "f"(x));
    return y;
}

// ---------------- prep: projections + wconv (unchanged from R8) -----------
template<int K>
__device__ __forceinline__ void proj8(const float* __restrict__ X,
                                      const float* __restrict__ W,
                                      const float* __restrict__ bias,
                                      float* __restrict__ out, int r0, int joff,
                                      float* __restrict__ sx) {
    const int j = threadIdx.x + joff;
    for (int idx = threadIdx.x; idx < 8 * K; idx += 320) {
        int r = idx / K, k = idx - r * K;
        sx[k * 8 + r] = X[(size_t)(r0 + r) * K + k];
    }
    __syncthreads();
    float acc[8];
    float bj = bias[j];
#pragma unroll
    for (int r = 0; r < 8; r++) acc[r] = bj;

    float wc[16], wn[16];
#pragma unroll
    for (int q = 0; q < 16; q++) wc[q] = W[(size_t)q * DJ + j];

#define FMA_BATCH(WREG, KBASE)                                          \
    _Pragma("unroll")                                                   \
    for (int q = 0; q < 16; q++) {                                      \
        float4 x0 = *(const float4*)&sx[((KBASE) + q) * 8];             \
        float4 x1 = *(const float4*)&sx[((KBASE) + q) * 8 + 4];         \
        acc[0] = fmaf(x0.x, WREG[q], acc[0]);                           \
        acc[1] = fmaf(x0.y, WREG[q], acc[1]);                           \
        acc[2] = fmaf(x0.z, WREG[q], acc[2]);                           \
        acc[3] = fmaf(x0.w, WREG[q], acc[3]);                           \
        acc[4] = fmaf(x1.x, WREG[q], acc[4]);                           \
        acc[5] = fmaf(x1.y, WREG[q], acc[5]);                           \
        acc[6] = fmaf(x1.z, WREG[q], acc[6]);                           \
        acc[7] = fmaf(x1.w, WREG[q], acc[7]);                           \
    }

#pragma unroll 1
    for (int k0 = 0; k0 < K; k0 += 32) {
#pragma unroll
        for (int q = 0; q < 16; q++) wn[q] = W[(size_t)(k0 + 16 + q) * DJ + j];
        FMA_BATCH(wc, k0)
        if (k0 + 32 < K) {
#pragma unroll
            for (int q = 0; q < 16; q++) wc[q] = W[(size_t)(k0 + 32 + q) * DJ + j];
        }
        FMA_BATCH(wn, k0 + 16)
    }
#undef FMA_BATCH

#pragma unroll
    for (int r = 0; r < 8; r++) out[(size_t)(r0 + r) * DJ + j] = acc[r];
}

__global__ void __launch_bounds__(320, 3) prep_kernel(const float* __restrict__ enc,
                                                      const float* __restrict__ W_enc,
                                                      const float* __restrict__ b_enc,
                                                      const float* __restrict__ pred,
                                                      const float* __restrict__ W_pred,
                                                      const float* __restrict__ b_pred,
                                                      const float* __restrict__ W_out) {
    __shared__ float sx[8 * DPRED];
    const int bx = blockIdx.x;
    if (bx < 256) {
        proj8<DENC>(enc, W_enc, b_enc, g_encP, (bx >> 1) * 8, (bx & 1) * 320, sx);
    } else if (bx < 320) {
        int bb = bx - 256;
        proj8<DPRED>(pred, W_pred, b_pred, g_predP, (bb >> 1) * 8, (bb & 1) * 320, sx);
    } else {
        for (int idx = (bx - 320) * 320 + threadIdx.x; idx < DV * DJ; idx += 64 * 320) {
            int k = idx >> 10;
            int v = idx & 1023;
            g_Wh[v * DJ + k] = __float2half_rn(W_out[idx]);
        }
    }
}

// ============== fused GEMM: A resident in smem (tanh computed in-kernel) ==
// One CTA per 128-row M-block (512 CTAs). Smem: A 128x640 fp16 (160KB, ten
// SW128 16KB chunks) + 3x16KB ring (pred staging, then B stream) + enc 5KB
// + bias 4KB. Main loop: 8 N-chunks x 10 K-chunks, B-only streaming.
// 8 warps as 2(M)x4(N), warp tile 64x32.

#define A_OFF    0
#define RING_OFF 163840
#define ENC_OFF  (RING_OFF + 3*16384)       // 212992
#define BIAS_OFF (ENC_OFF + 5120)           // 218112
#define FUSED_SMEM (BIAS_OFF + 4096)        // 222208

__device__ __forceinline__ uint32_t smem_u32(const void* p) {
    uint32_t a;
    asm("{ .reg .u64 t; cvta.to.shared.u64 t, %1; cvt.u32.u64 %0, t; }" : "=r"(a) : "l"(p));
    return a;
}
__device__ __forceinline__ uint32_t swz(uint32_t o) { return o ^ ((o >> 3) & 0x70); }
__device__ __forceinline__ void cp16(uint32_t dst, const void* src) {
    asm volatile("cp.async.cg.shared.global [%0], [%1], 16;" :: "r"(dst), "l"(src));
}
__device__ __forceinline__ void ldsm4(uint32_t& r0, uint32_t& r1, uint32_t& r2,
                                      uint32_t& r3, uint32_t a) {
    asm volatile("ldmatrix.sync.aligned.m8n8.x4.shared.b16 {%0,%1,%2,%3}, [%4];"
                 : "=r"(r0), "=r"(r1), "=r"(r2), "=r"(r3) : "r"(a));
}
__device__ __forceinline__ void mma16816(float c[4], const uint32_t a[4], const uint32_t b[2]) {
    asm volatile(
        "mma.sync.aligned.m16n8k16.row.col.f32.f16.f16.f32 "
        "{%0,%1,%2,%3}, {%4,%5,%6,%7}, {%8,%9}, {%0,%1,%2,%3};\n"
        : "+f"(c[0]), "+f"(c[1]), "+f"(c[2]), "+f"(c[3])
        : "r"(a[0]), "r"(a[1]), "r"(a[2]), "r"(a[3]), "r"(b[0]), "r"(b[1]));
}

__global__ void __launch_bounds__(256, 1) gemm_fused(const float* __restrict__ b_out,
                                                     float* __restrict__ out) {
    extern __shared__ char ds[];
    const uint32_t sbase = smem_u32(ds);
    const int tid  = threadIdx.x;
    const int warp = tid >> 5;
    const int lane = tid & 31;
    const int g = lane >> 2;
    const int t = lane & 3;
    const int wm = (warp >> 2) * 64;            // 2 M-warps
    const int wn = (warp & 3) * 32;             // 4 N-warps
    const int m0  = blockIdx.x * 128;
    const int bt0 = blockIdx.x * 2;
    const int b   = bt0 >> 8;

    // ---- preload enc rows (2x640 f32) and bias (1024 f32) ----
    {
        const float4* eg = (const float4*)(g_encP + (size_t)bt0 * DJ);
        float4* es = (float4*)(ds + ENC_OFF);
        for (int i = tid; i < 320; i += 256) es[i] = eg[i];
        float* bs = (float*)(ds + BIAS_OFF);
#pragma unroll
        for (int q = 0; q < 4; q++) bs[tid + 256 * q] = b_out[tid + 256 * q];
    }

    // ---- stage A: compute 128x640 fp16 tanh tile into smem ----
    auto issueP = [&](int kc) {     // pred chunk 64 rows x 64 k (f32, linear)
        uint32_t st = sbase + RING_OFF + (kc % 3) * 16384;
        const float* pg = g_predP + (size_t)(b * DU) * DJ + kc * 64;
#pragma unroll
        for (int q = 0; q < 4; q++) {
            int id = tid + 256 * q;             // 1024 float4
            int row = id >> 4, c = id & 15;
            cp16(st + row * 256 + c * 16, pg + (size_t)row * DJ + c * 4);
        }
        asm volatile("cp.async.commit_group;" ::: "memory");
    };
    issueP(0); issueP(1);
#pragma unroll 1
    for (int kc = 0; kc < 10; kc++) {
        asm volatile("cp.async.wait_group 1;" ::: "memory");
        __syncthreads();
        if (kc + 2 < 10) issueP(kc + 2);
        else asm volatile("cp.async.commit_group;" ::: "memory");
        const float* ps = (const float*)(ds + RING_OFF + (kc % 3) * 16384);
        const float* es = (const float*)(ds + ENC_OFF);
#pragma unroll
        for (int q = 0; q < 4; q++) {
            int id = tid + 256 * q;             // 1024 int4 outputs
            int row = id >> 3, c16 = id & 7;
            int btl = row >> 6, u = row & 63;
            const float4* e = (const float4*)(es + btl * DJ + kc * 64 + c16 * 8);
            const float4* p = (const float4*)(ps + u * 64 + c16 * 8);
            float4 e0 = e[0], e1 = e[1];
            float4 p0 = p[0], p1 = p[1];
            __half2 q0 = __floats2half2_rn(tanha(e0.x + p0.x), tanha(e0.y + p0.y));
            __half2 q1 = __floats2half2_rn(tanha(e0.z + p0.z), tanha(e0.w + p0.w));
            __half2 q2 = __floats2half2_rn(tanha(e1.x + p1.x), tanha(e1.y + p1.y));
            __half2 q3 = __floats2half2_rn(tanha(e1.z + p1.z), tanha(e1.w + p1.w));
            int4 v;
            v.x = *(int*)&q0; v.y = *(int*)&q1; v.z = *(int*)&q2; v.w = *(int*)&q3;
            *(int4*)(ds + A_OFF + kc * 16384 + swz(row * 128 + c16 * 16)) = v;
        }
    }
    asm volatile("cp.async.wait_group 0;" ::: "memory");
    __syncthreads();

    // ---- main loop: stream B, 8 n-chunks x 10 k-chunks ----
    auto issueB = [&](int tt) {
        int nc = tt / 10, kt = tt - nc * 10;
        uint32_t st = sbase + RING_OFF + (tt % 3) * 16384;
        const __half* bg = g_Wh + (size_t)(nc * 128) * DJ + kt * 64;
#pragma unroll
        for (int q = 0; q < 4; q++) {
            int id = tid + 256 * q;             // 1024 int4
            int row = id >> 3, c16 = id & 7;
            cp16(st + swz(row * 128 + c16 * 16), bg + (size_t)row * DJ + c16 * 8);
        }
        asm volatile("cp.async.commit_group;" ::: "memory");
    };
    issueB(0); issueB(1);

    const int rowA  = wm + (lane & 15);
    const uint32_t kbA  = (lane >> 4) * 16;
    const uint32_t xorA = (uint32_t)(rowA & 7) * 16;
    const int rowB  = wn + (lane & 7) + ((lane >> 4) << 3);
    const uint32_t kbB  = ((lane >> 3) & 1) * 16;
    const uint32_t xorB = (uint32_t)(lane & 7) * 16;

    float acc[4][4][4];
#pragma unroll
    for (int i = 0; i < 4; i++)
#pragma unroll
        for (int j = 0; j < 4; j++)
#pragma unroll
            for (int q = 0; q < 4; q++) acc[i][j][q] = 0.0f;

    const float* bs = (const float*)(ds + BIAS_OFF);

#pragma unroll 1
    for (int tt = 0; tt < 80; tt++) {
        asm volatile("cp.async.wait_group 1;" ::: "memory");
        __syncthreads();
        if (tt + 2 < 80) issueB(tt + 2);
        else asm volatile("cp.async.commit_group;" ::: "memory");

        const int nc = tt / 10, kt = tt - nc * 10;
        const uint32_t stA = sbase + A_OFF + kt * 16384;
        const uint32_t stB = sbase + RING_OFF + (tt % 3) * 16384;
#pragma unroll
        for (int ks = 0; ks < 4; ks++) {
            const uint32_t kb = ks * 32;
            uint32_t a[4][4];
#pragma unroll
            for (int i = 0; i < 4; i++)
                ldsm4(a[i][0], a[i][1], a[i][2], a[i][3],
                      stA + (uint32_t)(rowA + i * 16) * 128 + ((kb + kbA) ^ xorA));
            uint32_t bf[4][2];
#pragma unroll
            for (int jp = 0; jp < 2; jp++) {
                uint32_t r0, r1, r2, r3;
                ldsm4(r0, r1, r2, r3,
                      stB + (uint32_t)(rowB + jp * 16) * 128 + ((kb + kbB) ^ xorB));
                bf[2*jp][0] = r0; bf[2*jp][1] = r1;
                bf[2*jp+1][0] = r2; bf[2*jp+1][1] = r3;
            }
#pragma unroll
            for (int i = 0; i < 4; i++)
#pragma unroll
                for (int j = 0; j < 4; j++)
                    mma16816(acc[i][j], a[i], bf[j]);
        }

        if (kt == 9) {   // epilogue for this n-chunk
            const int ncol = nc * 128;
#pragma unroll
            for (int j = 0; j < 4; j++) {
                int col = ncol + wn + j * 8 + 2 * t;
                float bo0 = bs[col], bo1 = bs[col + 1];
#pragma unroll
                for (int i = 0; i < 4; i++) {
                    int r0 = m0 + wm + i * 16 + g;
                    float2 v0, v1;
                    v0.x = fminf(fmaxf(acc[i][j][0] + bo0, -15.0f), 15.0f);
                    v0.y = fminf(fmaxf(acc[i][j][1] + bo1, -15.0f), 15.0f);
                    v1.x = fminf(fmaxf(acc[i][j][2] + bo0, -15.0f), 15.0f);
                    v1.y = fminf(fmaxf(acc[i][j][3] + bo1, -15.0f), 15.0f);
                    *(float2*)(out + (size_t)r0 * DV + col)       = v0;
                    *(float2*)(out + (size_t)(r0 + 8) * DV + col) = v1;
#pragma unroll
                    for (int q = 0; q < 4; q++) acc[i][j][q] = 0.0f;
                }
            }
        }
    }
}

// ---------------- launch ---------------------------------------------------
extern "C" void kernel_launch(void* const* d_in, const int* in_sizes, int n_in,
                              void* d_out, int out_size) {
    const float* enc    = (const float*)d_in[0];
    const float* pred   = (const float*)d_in[1];
    const float* W_enc  = (const float*)d_in[2];
    const float* b_enc  = (const float*)d_in[3];
    const float* W_pred = (const float*)d_in[4];
    const float* b_pred = (const float*)d_in[5];
    const float* W_out  = (const float*)d_in[6];
    const float* b_out  = (const float*)d_in[7];
    float* out = (float*)d_out;

    cudaFuncSetAttribute(gemm_fused, cudaFuncAttributeMaxDynamicSharedMemorySize, FUSED_SMEM);

    prep_kernel<<<384, 320>>>(enc, W_enc, b_enc, pred, W_pred, b_pred, W_out);
    gemm_fused<<<M_TOTAL / 128, 256, FUSED_SMEM>>>(b_out, out);
}

// round 10
// speedup vs baseline: 2.1225x; 2.1225x over previous
#include <cuda_runtime.h>
#include <cuda_fp16.h>
#include <cstdint>

#define DB 4
#define DT 256
#define DU 64
#define DENC 512
#define DPRED 640
#define DJ 640
#define DV 1024
#define BT (DB*DT)        // 1024 enc rows
#define BUROWS (DB*DU)    // 256 pred rows
#define M_TOTAL (BT*DU)   // 65536 joint rows

// ---------------- device scratch (no allocations allowed) ----------------
__device__ float  g_encP[BT * DJ];                 // 2.6 MB
__device__ float  g_predP[BUROWS * DJ];            // 0.66 MB
__device__ __half g_joint[(size_t)M_TOTAL * DJ];   // 84 MB
__device__ __half g_Wh[DV * DJ];                   // W_out^T [v][k]
__device__ __half g_encH[BT * DENC];               // enc fp16 [m][k]
__device__ __half g_predH[BUROWS * DPRED];         // pred fp16 [m][k]
__device__ __half g_WeH[DJ * DENC];                // W_enc^T fp16 [j][k]
__device__ __half g_WpH[DJ * DPRED];               // W_pred^T fp16 [j][k]

// ---------------- tanh via MUFU.TANH --------------------------------------
__device__ __forceinline__ float tanha(float x) {
    float y;
    asm("tanh.approx.f32 %0, %1;" : "=f"(y) : "f"(x));
    return y;
}

// ---------------- convert: fp32->fp16 copies + weight transposes ----------
__global__ void __launch_bounds__(256) convert_kernel(const float* __restrict__ enc,
                                                      const float* __restrict__ pred,
                                                      const float* __restrict__ W_enc,
                                                      const float* __restrict__ W_pred,
                                                      const float* __restrict__ W_out) {
    const int bx = blockIdx.x, tid = threadIdx.x;
    if (bx < 64) {                       // enc: 131072 float4
        const float4* src = (const float4*)enc;
        for (int i = bx * 256 + tid; i < (BT * DENC) / 4; i += 64 * 256) {
            float4 v = src[i];
            __half2 h0 = __floats2half2_rn(v.x, v.y);
            __half2 h1 = __floats2half2_rn(v.z, v.w);
            int2 o; o.x = *(int*)&h0; o.y = *(int*)&h1;
            ((int2*)g_encH)[i] = o;
        }
    } else if (bx < 80) {                // pred: 40960 float4
        const float4* src = (const float4*)pred;
        for (int i = (bx - 64) * 256 + tid; i < (BUROWS * DPRED) / 4; i += 16 * 256) {
            float4 v = src[i];
            __half2 h0 = __floats2half2_rn(v.x, v.y);
            __half2 h1 = __floats2half2_rn(v.z, v.w);
            int2 o; o.x = *(int*)&h0; o.y = *(int*)&h1;
            ((int2*)g_predH)[i] = o;
        }
    } else if (bx < 144) {               // W_enc^T: 512x640
        for (int idx = (bx - 80) * 256 + tid; idx < DENC * DJ; idx += 64 * 256) {
            int k = idx / DJ, j = idx - k * DJ;
            g_WeH[(size_t)j * DENC + k] = __float2half_rn(W_enc[idx]);
        }
    } else if (bx < 224) {               // W_pred^T: 640x640
        for (int idx = (bx - 144) * 256 + tid; idx < DPRED * DJ; idx += 80 * 256) {
            int k = idx / DJ, j = idx - k * DJ;
            g_WpH[(size_t)j * DPRED + k] = __float2half_rn(W_pred[idx]);
        }
    } else {                             // W_out^T: 640x1024
        for (int idx = (bx - 224) * 256 + tid; idx < DJ * DV; idx += 128 * 256) {
            int k = idx >> 10, v = idx & 1023;
            g_Wh[(size_t)v * DJ + k] = __float2half_rn(W_out[idx]);
        }
    }
}

// ---------------- shared GEMM helpers --------------------------------------
__device__ __forceinline__ uint32_t smem_u32(const void* p) {
    uint32_t a;
    asm("{ .reg .u64 t; cvta.to.shared.u64 t, %1; cvt.u32.u64 %0, t; }" : "=r"(a) : "l"(p));
    return a;
}
__device__ __forceinline__ uint32_t swz(uint32_t o) { return o ^ ((o >> 3) & 0x70); }
__device__ __forceinline__ void cp16(uint32_t dst, const void* src) {
    asm volatile("cp.async.cg.shared.global [%0], [%1], 16;" :: "r"(dst), "l"(src));
}
__device__ __forceinline__ void ldsm4(uint32_t& r0, uint32_t& r1, uint32_t& r2,
                                      uint32_t& r3, uint32_t a) {
    asm volatile("ldmatrix.sync.aligned.m8n8.x4.shared.b16 {%0,%1,%2,%3}, [%4];"
                 : "=r"(r0), "=r"(r1), "=r"(r2), "=r"(r3) : "r"(a));
}
__device__ __forceinline__ void mma16816(float c[4], const uint32_t a[4], const uint32_t b[2]) {
    asm volatile(
        "mma.sync.aligned.m16n8k16.row.col.f32.f16.f16.f32 "
        "{%0,%1,%2,%3}, {%4,%5,%6,%7}, {%8,%9}, {%0,%1,%2,%3};\n"
        : "+f"(c[0]), "+f"(c[1]), "+f"(c[2]), "+f"(c[3])
        : "r"(a[0]), "r"(a[1]), "r"(a[2]), "r"(a[3]), "r"(b[0]), "r"(b[1]));
}

// ---------------- proj via tensor cores ------------------------------------
// 64x64 tile per CTA, 4 warps as 2(M)x2(N), warp tile 32x32, BK=64 halves.
// blocks [0,160): encP (K=512); [160,200): predP (K=640). fp32+bias epilogue.
#define PROJ_SMEM (3 * 16384)
__global__ void __launch_bounds__(128) proj_mma(const float* __restrict__ b_enc,
                                                const float* __restrict__ b_pred) {
    extern __shared__ char ds[];
    const uint32_t sbase = smem_u32(ds);
    const int tid  = threadIdx.x;
    const int warp = tid >> 5;
    const int lane = tid & 31;
    const int g = lane >> 2;
    const int t = lane & 3;
    const int wm = (warp >> 1) * 32;
    const int wn = (warp & 1) * 32;

    const __half *Asrc, *Bsrc;
    const float* bias;
    float* dst;
    int m0, n0, K, ktiles;
    const int bx = blockIdx.x;
    if (bx < 160) {
        m0 = (bx / 10) * 64; n0 = (bx % 10) * 64;
        K = DENC; ktiles = 8;
        Asrc = g_encH; Bsrc = g_WeH; bias = b_enc; dst = g_encP;
    } else {
        int bb = bx - 160;
        m0 = (bb / 10) * 64; n0 = (bb % 10) * 64;
        K = DPRED; ktiles = 10;
        Asrc = g_predH; Bsrc = g_WpH; bias = b_pred; dst = g_predP;
    }

    auto load_stage = [&](int s, int kt) {
        const uint32_t stA = sbase + s * 16384;
        const uint32_t stB = stA + 8192;
        const int koff = kt * 64;
#pragma unroll
        for (int q = 0; q < 4; q++) {
            int id = tid + 128 * q;
            int row = id >> 3, c16 = id & 7;
            cp16(stA + swz(row * 128 + c16 * 16), Asrc + (size_t)(m0 + row) * K + koff + c16 * 8);
        }
#pragma unroll
        for (int q = 0; q < 4; q++) {
            int id = tid + 128 * q;
            int row = id >> 3, c16 = id & 7;
            cp16(stB + swz(row * 128 + c16 * 16), Bsrc + (size_t)(n0 + row) * K + koff + c16 * 8);
        }
        asm volatile("cp.async.commit_group;" ::: "memory");
    };

    const int rowA  = wm + (lane & 15);
    const uint32_t kbA  = (lane >> 4) * 16;
    const uint32_t xorA = (uint32_t)(rowA & 7) * 16;
    const int rowB  = wn + (lane & 7) + ((lane >> 4) << 3);
    const uint32_t kbB  = ((lane >> 3) & 1) * 16;
    const uint32_t xorB = (uint32_t)(lane & 7) * 16;

    float acc[2][4][4];
#pragma unroll
    for (int i = 0; i < 2; i++)
#pragma unroll
        for (int j = 0; j < 4; j++)
#pragma unroll
            for (int q = 0; q < 4; q++) acc[i][j][q] = 0.0f;

    auto compute = [&](int s) {
        const uint32_t stA = sbase + s * 16384;
        const uint32_t stB = stA + 8192;
#pragma unroll
        for (int ks = 0; ks < 4; ks++) {
            const uint32_t kb = ks * 32;
            uint32_t a[2][4];
#pragma unroll
            for (int i = 0; i < 2; i++)
                ldsm4(a[i][0], a[i][1], a[i][2], a[i][3],
                      stA + (uint32_t)(rowA + i * 16) * 128 + ((kb + kbA) ^ xorA));
            uint32_t b[4][2];
#pragma unroll
            for (int jp = 0; jp < 2; jp++) {
                uint32_t r0, r1, r2, r3;
                ldsm4(r0, r1, r2, r3,
                      stB + (uint32_t)(rowB + jp * 16) * 128 + ((kb + kbB) ^ xorB));
                b[2*jp][0] = r0; b[2*jp][1] = r1;
                b[2*jp+1][0] = r2; b[2*jp+1][1] = r3;
            }
#pragma unroll
            for (int i = 0; i < 2; i++)
#pragma unroll
                for (int j = 0; j < 4; j++)
                    mma16816(acc[i][j], a[i], b[j]);
        }
    };

    load_stage(0, 0);
    load_stage(1, 1);
#pragma unroll 1
    for (int kt = 0; kt < ktiles; kt++) {
        asm volatile("cp.async.wait_group 1;" ::: "memory");
        __syncthreads();
        if (kt + 2 < ktiles) load_stage((kt + 2) % 3, kt + 2);
        else asm volatile("cp.async.commit_group;" ::: "memory");
        compute(kt % 3);
    }

#pragma unroll
    for (int j = 0; j < 4; j++) {
        int col = n0 + wn + j * 8 + 2 * t;
        float bo0 = __ldg(bias + col), bo1 = __ldg(bias + col + 1);
#pragma unroll
        for (int i = 0; i < 2; i++) {
            int r0 = m0 + wm + i * 16 + g;
            float2 v0, v1;
            v0.x = acc[i][j][0] + bo0; v0.y = acc[i][j][1] + bo1;
            v1.x = acc[i][j][2] + bo0; v1.y = acc[i][j][3] + bo1;
            *(float2*)(dst + (size_t)r0 * DJ + col)       = v0;
            *(float2*)(dst + (size_t)(r0 + 8) * DJ + col) = v1;
        }
    }
}

// ---------------- joint = tanh(encP + predP) -> fp16 (flat, MUFU) --------
__global__ void __launch_bounds__(256) joint_tanh_kernel() {
    int idx = blockIdx.x * 256 + threadIdx.x;
    int m  = idx / 80;
    int kq = (idx - m * 80) * 8;
    int bt = m >> 6;
    int u  = m & 63;
    int b  = bt >> 8;
    const float4* e = (const float4*)(g_encP  + (size_t)bt * DJ + kq);
    const float4* p = (const float4*)(g_predP + (size_t)(b * DU + u) * DJ + kq);
    float4 e0 = e[0], e1 = e[1];
    float4 p0 = p[0], p1 = p[1];
    __half2 q0 = __floats2half2_rn(tanha(e0.x + p0.x), tanha(e0.y + p0.y));
    __half2 q1 = __floats2half2_rn(tanha(e0.z + p0.z), tanha(e0.w + p0.w));
    __half2 q2 = __floats2half2_rn(tanha(e1.x + p1.x), tanha(e1.y + p1.y));
    __half2 q3 = __floats2half2_rn(tanha(e1.z + p1.z), tanha(e1.w + p1.w));
    int4 v;
    v.x = *(int*)&q0; v.y = *(int*)&q1; v.z = *(int*)&q2; v.w = *(int*)&q3;
    *(int4*)(g_joint + (size_t)m * DJ + kq) = v;
}

// ==================== main GEMM (unchanged R6/R8: ~218us, tensor-bound) ===
#define BM 128
#define BN 128
#define BK 64
#define KTILES 10
#define ASZ (BM*BK*2)
#define BSZ (BN*BK*2)
#define STG (ASZ+BSZ)
#define STAGES 3
#define DYN_SMEM (STAGES*STG)

__global__ void __launch_bounds__(128, 2) gemm_lm(const float* __restrict__ b_out,
                                                  float* __restrict__ out) {
    extern __shared__ char ds[];
    const uint32_t sbase = smem_u32(ds);
    const int tid  = threadIdx.x;
    const int warp = tid >> 5;
    const int lane = tid & 31;
    const int g = lane >> 2;
    const int t = lane & 3;
    const int wm = (warp >> 1) * 64;
    const int wn = (warp & 1) * 64;
    const int m0 = blockIdx.y * BM;
    const int n0 = blockIdx.x * BN;

    const __half* aG = g_joint + (size_t)m0 * DJ;
    const __half* bG = g_Wh    + (size_t)n0 * DJ;

    auto load_stage = [&](int s, int kt) {
        const uint32_t stA = sbase + s * STG;
        const uint32_t stB = stA + ASZ;
        const int koff = kt * BK;
#pragma unroll
        for (int q = 0; q < 8; q++) {
            int id = tid + 128 * q;
            int row = id >> 3, c = id & 7;
            cp16(stA + swz(row * 128 + c * 16), aG + (size_t)row * DJ + koff + c * 8);
        }
#pragma unroll
        for (int q = 0; q < 8; q++) {
            int id = tid + 128 * q;
            int row = id >> 3, c = id & 7;
            cp16(stB + swz(row * 128 + c * 16), bG + (size_t)row * DJ + koff + c * 8);
        }
        asm volatile("cp.async.commit_group;" ::: "memory");
    };

    const int rowA  = wm + (lane & 15);
    const uint32_t kbA  = (lane >> 4) * 16;
    const uint32_t xorA = (uint32_t)(rowA & 7) * 16;
    const int rowB  = wn + (lane & 7) + ((lane >> 4) << 3);
    const uint32_t kbB  = ((lane >> 3) & 1) * 16;
    const uint32_t xorB = (uint32_t)(lane & 7) * 16;

    float acc[4][8][4];
#pragma unroll
    for (int i = 0; i < 4; i++)
#pragma unroll
        for (int j = 0; j < 8; j++)
#pragma unroll
            for (int q = 0; q < 4; q++) acc[i][j][q] = 0.0f;

    auto compute = [&](int s) {
        const uint32_t stA = sbase + s * STG;
        const uint32_t stB = stA + ASZ;
#pragma unroll
        for (int ks = 0; ks < 4; ks++) {
            const uint32_t kb = ks * 32;
            uint32_t a[4][4];
#pragma unroll
            for (int i = 0; i < 4; i++)
                ldsm4(a[i][0], a[i][1], a[i][2], a[i][3],
                      stA + (uint32_t)(rowA + i * 16) * 128 + ((kb + kbA) ^ xorA));
            uint32_t b[8][2];
#pragma unroll
            for (int jp = 0; jp < 4; jp++) {
                uint32_t r0, r1, r2, r3;
                ldsm4(r0, r1, r2, r3,
                      stB + (uint32_t)(rowB + jp * 16) * 128 + ((kb + kbB) ^ xorB));
                b[2*jp][0] = r0; b[2*jp][1] = r1;
                b[2*jp+1][0] = r2; b[2*jp+1][1] = r3;
            }
#pragma unroll
            for (int i = 0; i < 4; i++)
#pragma unroll
                for (int j = 0; j < 8; j++)
                    mma16816(acc[i][j], a[i], b[j]);
        }
    };

    load_stage(0, 0);
    load_stage(1, 1);
#pragma unroll 1
    for (int kt = 0; kt < KTILES; kt++) {
        asm volatile("cp.async.wait_group 1;" ::: "memory");
        __syncthreads();
        if (kt + 2 < KTILES) load_stage((kt + 2) % 3, kt + 2);
        else asm volatile("cp.async.commit_group;" ::: "memory");
        compute(kt % 3);
    }

#pragma unroll
    for (int j = 0; j < 8; j++) {
        int col = n0 + wn + j * 8 + 2 * t;
        float bo0 = __ldg(b_out + col), bo1 = __ldg(b_out + col + 1);
#pragma unroll
        for (int i = 0; i < 4; i++) {
            int r0 = m0 + wm + i * 16 + g;
            float2 v0, v1;
            v0.x = fminf(fmaxf(acc[i][j][0] + bo0, -15.0f), 15.0f);
            v0.y = fminf(fmaxf(acc[i][j][1] + bo1, -15.0f), 15.0f);
            v1.x = fminf(fmaxf(acc[i][j][2] + bo0, -15.0f), 15.0f);
            v1.y = fminf(fmaxf(acc[i][j][3] + bo1, -15.0f), 15.0f);
            *(float2*)(out + (size_t)r0 * DV + col)       = v0;
            *(float2*)(out + (size_t)(r0 + 8) * DV + col) = v1;
        }
    }
}

// ---------------- launch ---------------------------------------------------
extern "C" void kernel_launch(void* const* d_in, const int* in_sizes, int n_in,
                              void* d_out, int out_size) {
    const float* enc    = (const float*)d_in[0];
    const float* pred   = (const float*)d_in[1];
    const float* W_enc  = (const float*)d_in[2];
    const float* b_enc  = (const float*)d_in[3];
    const float* W_pred = (const float*)d_in[4];
    const float* b_pred = (const float*)d_in[5];
    const float* W_out  = (const float*)d_in[6];
    const float* b_out  = (const float*)d_in[7];
    float* out = (float*)d_out;

    cudaFuncSetAttribute(gemm_lm, cudaFuncAttributeMaxDynamicSharedMemorySize, DYN_SMEM);
    cudaFuncSetAttribute(proj_mma, cudaFuncAttributeMaxDynamicSharedMemorySize, PROJ_SMEM);

    convert_kernel<<<352, 256>>>(enc, pred, W_enc, W_pred, W_out);
    proj_mma<<<200, 128, PROJ_SMEM>>>(b_enc, b_pred);
    joint_tanh_kernel<<<(M_TOTAL * 80) / 256, 256>>>();
    gemm_lm<<<dim3(DV / BN, M_TOTAL / BM), 128, DYN_SMEM>>>(b_out, out);
}

// round 11
// speedup vs baseline: 2.1465x; 1.0113x over previous
#include <cuda_runtime.h>
#include <cuda_fp16.h>
#include <cstdint>

#define DB 4
#define DT 256
#define DU 64
#define DENC 512
#define DPRED 640
#define DJ 640
#define DV 1024
#define BT (DB*DT)        // 1024 enc rows
#define BUROWS (DB*DU)    // 256 pred rows
#define M_TOTAL (BT*DU)   // 65536 joint rows

// ---------------- device scratch (no allocations allowed) ----------------
__device__ float  g_encP[BT * DJ];                 // 2.6 MB
__device__ float  g_predP[BUROWS * DJ];            // 0.66 MB
__device__ __half g_joint[(size_t)M_TOTAL * DJ];   // 84 MB
__device__ __half g_Wh[DV * DJ];                   // W_out^T [v][k]
__device__ __half g_encH[BT * DENC];               // enc fp16 [m][k]
__device__ __half g_predH[BUROWS * DPRED];         // pred fp16 [m][k]
__device__ __half g_WeH[DJ * DENC];                // W_enc^T fp16 [j][k]
__device__ __half g_WpH[DJ * DPRED];               // W_pred^T fp16 [j][k]

// ---------------- tanh via MUFU.TANH --------------------------------------
__device__ __forceinline__ float tanha(float x) {
    float y;
    asm("tanh.approx.f32 %0, %1;" : "=f"(y) : "f"(x));
    return y;
}

// ---------------- convert: fp32->fp16 copies + weight transposes ----------
__global__ void __launch_bounds__(256) convert_kernel(const float* __restrict__ enc,
                                                      const float* __restrict__ pred,
                                                      const float* __restrict__ W_enc,
                                                      const float* __restrict__ W_pred,
                                                      const float* __restrict__ W_out) {
    const int bx = blockIdx.x, tid = threadIdx.x;
    if (bx < 64) {                       // enc: 131072 float4
        const float4* src = (const float4*)enc;
        for (int i = bx * 256 + tid; i < (BT * DENC) / 4; i += 64 * 256) {
            float4 v = src[i];
            __half2 h0 = __floats2half2_rn(v.x, v.y);
            __half2 h1 = __floats2half2_rn(v.z, v.w);
            int2 o; o.x = *(int*)&h0; o.y = *(int*)&h1;
            ((int2*)g_encH)[i] = o;
        }
    } else if (bx < 80) {                // pred: 40960 float4
        const float4* src = (const float4*)pred;
        for (int i = (bx - 64) * 256 + tid; i < (BUROWS * DPRED) / 4; i += 16 * 256) {
            float4 v = src[i];
            __half2 h0 = __floats2half2_rn(v.x, v.y);
            __half2 h1 = __floats2half2_rn(v.z, v.w);
            int2 o; o.x = *(int*)&h0; o.y = *(int*)&h1;
            ((int2*)g_predH)[i] = o;
        }
    } else if (bx < 144) {               // W_enc^T: 512x640
        for (int idx = (bx - 80) * 256 + tid; idx < DENC * DJ; idx += 64 * 256) {
            int k = idx / DJ, j = idx - k * DJ;
            g_WeH[(size_t)j * DENC + k] = __float2half_rn(W_enc[idx]);
        }
    } else if (bx < 224) {               // W_pred^T: 640x640
        for (int idx = (bx - 144) * 256 + tid; idx < DPRED * DJ; idx += 80 * 256) {
            int k = idx / DJ, j = idx - k * DJ;
            g_WpH[(size_t)j * DPRED + k] = __float2half_rn(W_pred[idx]);
        }
    } else {                             // W_out^T: 640x1024
        for (int idx = (bx - 224) * 256 + tid; idx < DJ * DV; idx += 128 * 256) {
            int k = idx >> 10, v = idx & 1023;
            g_Wh[(size_t)v * DJ + k] = __float2half_rn(W_out[idx]);
        }
    }
}

// ---------------- shared GEMM helpers --------------------------------------
__device__ __forceinline__ uint32_t smem_u32(const void* p) {
    uint32_t a;
    asm("{ .reg .u64 t; cvta.to.shared.u64 t, %1; cvt.u32.u64 %0, t; }" : "=r"(a) : "l"(p));
    return a;
}
__device__ __forceinline__ uint32_t swz(uint32_t o) { return o ^ ((o >> 3) & 0x70); }
__device__ __forceinline__ void cp16(uint32_t dst, const void* src) {
    asm volatile("cp.async.cg.shared.global [%0], [%1], 16;" :: "r"(dst), "l"(src));
}
__device__ __forceinline__ void ldsm4(uint32_t& r0, uint32_t& r1, uint32_t& r2,
                                      uint32_t& r3, uint32_t a) {
    asm volatile("ldmatrix.sync.aligned.m8n8.x4.shared.b16 {%0,%1,%2,%3}, [%4];"
                 : "=r"(r0), "=r"(r1), "=r"(r2), "=r"(r3) : "r"(a));
}
__device__ __forceinline__ void mma16816(float c[4], const uint32_t a[4], const uint32_t b[2]) {
    asm volatile(
        "mma.sync.aligned.m16n8k16.row.col.f32.f16.f16.f32 "
        "{%0,%1,%2,%3}, {%4,%5,%6,%7}, {%8,%9}, {%0,%1,%2,%3};\n"
        : "+f"(c[0]), "+f"(c[1]), "+f"(c[2]), "+f"(c[3])
        : "r"(a[0]), "r"(a[1]), "r"(a[2]), "r"(a[3]), "r"(b[0]), "r"(b[1]));
}

// ---------------- proj via tensor cores ------------------------------------
// 64x64 tile per CTA, 4 warps as 2(M)x2(N), warp tile 32x32, BK=64 halves.
#define PROJ_SMEM (3 * 16384)
__global__ void __launch_bounds__(128) proj_mma(const float* __restrict__ b_enc,
                                                const float* __restrict__ b_pred) {
    extern __shared__ char ds[];
    const uint32_t sbase = smem_u32(ds);
    const int tid  = threadIdx.x;
    const int warp = tid >> 5;
    const int lane = tid & 31;
    const int g = lane >> 2;
    const int t = lane & 3;
    const int wm = (warp >> 1) * 32;
    const int wn = (warp & 1) * 32;

    const __half *Asrc, *Bsrc;
    const float* bias;
    float* dst;
    int m0, n0, K, ktiles;
    const int bx = blockIdx.x;
    if (bx < 160) {
        m0 = (bx / 10) * 64; n0 = (bx % 10) * 64;
        K = DENC; ktiles = 8;
        Asrc = g_encH; Bsrc = g_WeH; bias = b_enc; dst = g_encP;
    } else {
        int bb = bx - 160;
        m0 = (bb / 10) * 64; n0 = (bb % 10) * 64;
        K = DPRED; ktiles = 10;
        Asrc = g_predH; Bsrc = g_WpH; bias = b_pred; dst = g_predP;
    }

    auto load_stage = [&](int s, int kt) {
        const uint32_t stA = sbase + s * 16384;
        const uint32_t stB = stA + 8192;
        const int koff = kt * 64;
#pragma unroll
        for (int q = 0; q < 4; q++) {
            int id = tid + 128 * q;
            int row = id >> 3, c16 = id & 7;
            cp16(stA + swz(row * 128 + c16 * 16), Asrc + (size_t)(m0 + row) * K + koff + c16 * 8);
        }
#pragma unroll
        for (int q = 0; q < 4; q++) {
            int id = tid + 128 * q;
            int row = id >> 3, c16 = id & 7;
            cp16(stB + swz(row * 128 + c16 * 16), Bsrc + (size_t)(n0 + row) * K + koff + c16 * 8);
        }
        asm volatile("cp.async.commit_group;" ::: "memory");
    };

    const int rowA  = wm + (lane & 15);
    const uint32_t kbA  = (lane >> 4) * 16;
    const uint32_t xorA = (uint32_t)(rowA & 7) * 16;
    const int rowB  = wn + (lane & 7) + ((lane >> 4) << 3);
    const uint32_t kbB  = ((lane >> 3) & 1) * 16;
    const uint32_t xorB = (uint32_t)(lane & 7) * 16;

    float acc[2][4][4];
#pragma unroll
    for (int i = 0; i < 2; i++)
#pragma unroll
        for (int j = 0; j < 4; j++)
#pragma unroll
            for (int q = 0; q < 4; q++) acc[i][j][q] = 0.0f;

    auto compute = [&](int s) {
        const uint32_t stA = sbase + s * 16384;
        const uint32_t stB = stA + 8192;
#pragma unroll
        for (int ks = 0; ks < 4; ks++) {
            const uint32_t kb = ks * 32;
            uint32_t a[2][4];
#pragma unroll
            for (int i = 0; i < 2; i++)
                ldsm4(a[i][0], a[i][1], a[i][2], a[i][3],
                      stA + (uint32_t)(rowA + i * 16) * 128 + ((kb + kbA) ^ xorA));
            uint32_t b[4][2];
#pragma unroll
            for (int jp = 0; jp < 2; jp++) {
                uint32_t r0, r1, r2, r3;
                ldsm4(r0, r1, r2, r3,
                      stB + (uint32_t)(rowB + jp * 16) * 128 + ((kb + kbB) ^ xorB));
                b[2*jp][0] = r0; b[2*jp][1] = r1;
                b[2*jp+1][0] = r2; b[2*jp+1][1] = r3;
            }
#pragma unroll
            for (int i = 0; i < 2; i++)
#pragma unroll
                for (int j = 0; j < 4; j++)
                    mma16816(acc[i][j], a[i], b[j]);
        }
    };

    load_stage(0, 0);
    load_stage(1, 1);
#pragma unroll 1
    for (int kt = 0; kt < ktiles; kt++) {
        asm volatile("cp.async.wait_group 1;" ::: "memory");
        __syncthreads();
        if (kt + 2 < ktiles) load_stage((kt + 2) % 3, kt + 2);
        else asm volatile("cp.async.commit_group;" ::: "memory");
        compute(kt % 3);
    }

#pragma unroll
    for (int j = 0; j < 4; j++) {
        int col = n0 + wn + j * 8 + 2 * t;
        float bo0 = __ldg(bias + col), bo1 = __ldg(bias + col + 1);
#pragma unroll
        for (int i = 0; i < 2; i++) {
            int r0 = m0 + wm + i * 16 + g;
            float2 v0, v1;
            v0.x = acc[i][j][0] + bo0; v0.y = acc[i][j][1] + bo1;
            v1.x = acc[i][j][2] + bo0; v1.y = acc[i][j][3] + bo1;
            *(float2*)(dst + (size_t)r0 * DJ + col)       = v0;
            *(float2*)(dst + (size_t)(r0 + 8) * DJ + col) = v1;
        }
    }
}

// ---------------- joint = tanh(encP + predP) -> fp16 (flat, MUFU) --------
__global__ void __launch_bounds__(256) joint_tanh_kernel() {
    int idx = blockIdx.x * 256 + threadIdx.x;
    int m  = idx / 80;
    int kq = (idx - m * 80) * 8;
    int bt = m >> 6;
    int u  = m & 63;
    int b  = bt >> 8;
    const float4* e = (const float4*)(g_encP  + (size_t)bt * DJ + kq);
    const float4* p = (const float4*)(g_predP + (size_t)(b * DU + u) * DJ + kq);
    float4 e0 = e[0], e1 = e[1];
    float4 p0 = p[0], p1 = p[1];
    __half2 q0 = __floats2half2_rn(tanha(e0.x + p0.x), tanha(e0.y + p0.y));
    __half2 q1 = __floats2half2_rn(tanha(e0.z + p0.z), tanha(e0.w + p0.w));
    __half2 q2 = __floats2half2_rn(tanha(e1.x + p1.x), tanha(e1.y + p1.y));
    __half2 q3 = __floats2half2_rn(tanha(e1.z + p1.z), tanha(e1.w + p1.w));
    int4 v;
    v.x = *(int*)&q0; v.y = *(int*)&q1; v.z = *(int*)&q2; v.w = *(int*)&q3;
    *(int4*)(g_joint + (size_t)m * DJ + kq) = v;
}

// ==================== main GEMM: 8 warps/CTA, 2 CTAs/SM ===================
// CTA tile 128x128, 8 warps as 2(M)x4(N), warp tile 64x32, BK=64, 3 stages.
// 16 warps/SM (4/SMSP) to fill the 36% idle tensor slots seen at 8 warps/SM.
#define BM 128
#define BN 128
#define BK 64
#define KTILES 10
#define ASZ (BM*BK*2)
#define BSZ (BN*BK*2)
#define STG (ASZ+BSZ)
#define STAGES 3
#define DYN_SMEM (STAGES*STG)

__global__ void __launch_bounds__(256, 2) gemm_lm(const float* __restrict__ b_out,
                                                  float* __restrict__ out) {
    extern __shared__ char ds[];
    const uint32_t sbase = smem_u32(ds);
    const int tid  = threadIdx.x;
    const int warp = tid >> 5;
    const int lane = tid & 31;
    const int g = lane >> 2;
    const int t = lane & 3;
    const int wm = (warp >> 2) * 64;            // 2 M-warps
    const int wn = (warp & 3) * 32;             // 4 N-warps
    const int m0 = blockIdx.y * BM;
    const int n0 = blockIdx.x * BN;

    const __half* aG = g_joint + (size_t)m0 * DJ;
    const __half* bG = g_Wh    + (size_t)n0 * DJ;

    auto load_stage = [&](int s, int kt) {
        const uint32_t stA = sbase + s * STG;
        const uint32_t stB = stA + ASZ;
        const int koff = kt * BK;
#pragma unroll
        for (int q = 0; q < 4; q++) {
            int id = tid + 256 * q;
            int row = id >> 3, c = id & 7;
            cp16(stA + swz(row * 128 + c * 16), aG + (size_t)row * DJ + koff + c * 8);
        }
#pragma unroll
        for (int q = 0; q < 4; q++) {
            int id = tid + 256 * q;
            int row = id >> 3, c = id & 7;
            cp16(stB + swz(row * 128 + c * 16), bG + (size_t)row * DJ + koff + c * 8);
        }
        asm volatile("cp.async.commit_group;" ::: "memory");
    };

    const int rowA  = wm + (lane & 15);
    const uint32_t kbA  = (lane >> 4) * 16;
    const uint32_t xorA = (uint32_t)(rowA & 7) * 16;
    const int rowB  = wn + (lane & 7) + ((lane >> 4) << 3);
    const uint32_t kbB  = ((lane >> 3) & 1) * 16;
    const uint32_t xorB = (uint32_t)(lane & 7) * 16;

    float acc[4][4][4];
#pragma unroll
    for (int i = 0; i < 4; i++)
#pragma unroll
        for (int j = 0; j < 4; j++)
#pragma unroll
            for (int q = 0; q < 4; q++) acc[i][j][q] = 0.0f;

    auto compute = [&](int s) {
        const uint32_t stA = sbase + s * STG;
        const uint32_t stB = stA + ASZ;
#pragma unroll
        for (int ks = 0; ks < 4; ks++) {
            const uint32_t kb = ks * 32;
            uint32_t a[4][4];
#pragma unroll
            for (int i = 0; i < 4; i++)
                ldsm4(a[i][0], a[i][1], a[i][2], a[i][3],
                      stA + (uint32_t)(rowA + i * 16) * 128 + ((kb + kbA) ^ xorA));
            uint32_t b[4][2];
#pragma unroll
            for (int jp = 0; jp < 2; jp++) {
                uint32_t r0, r1, r2, r3;
                ldsm4(r0, r1, r2, r3,
                      stB + (uint32_t)(rowB + jp * 16) * 128 + ((kb + kbB) ^ xorB));
                b[2*jp][0] = r0; b[2*jp][1] = r1;
                b[2*jp+1][0] = r2; b[2*jp+1][1] = r3;
            }
#pragma unroll
            for (int i = 0; i < 4; i++)
#pragma unroll
                for (int j = 0; j < 4; j++)
                    mma16816(acc[i][j], a[i], b[j]);
        }
    };

    load_stage(0, 0);
    load_stage(1, 1);
#pragma unroll 1
    for (int kt = 0; kt < KTILES; kt++) {
        asm volatile("cp.async.wait_group 1;" ::: "memory");
        __syncthreads();
        if (kt + 2 < KTILES) load_stage((kt + 2) % 3, kt + 2);
        else asm volatile("cp.async.commit_group;" ::: "memory");
        compute(kt % 3);
    }

#pragma unroll
    for (int j = 0; j < 4; j++) {
        int col = n0 + wn + j * 8 + 2 * t;
        float bo0 = __ldg(b_out + col), bo1 = __ldg(b_out + col + 1);
#pragma unroll
        for (int i = 0; i < 4; i++) {
            int r0 = m0 + wm + i * 16 + g;
            float2 v0, v1;
            v0.x = fminf(fmaxf(acc[i][j][0] + bo0, -15.0f), 15.0f);
            v0.y = fminf(fmaxf(acc[i][j][1] + bo1, -15.0f), 15.0f);
            v1.x = fminf(fmaxf(acc[i][j][2] + bo0, -15.0f), 15.0f);
            v1.y = fminf(fmaxf(acc[i][j][3] + bo1, -15.0f), 15.0f);
            *(float2*)(out + (size_t)r0 * DV + col)       = v0;
            *(float2*)(out + (size_t)(r0 + 8) * DV + col) = v1;
        }
    }
}

// ---------------- launch ---------------------------------------------------
extern "C" void kernel_launch(void* const* d_in, const int* in_sizes, int n_in,
                              void* d_out, int out_size) {
    const float* enc    = (const float*)d_in[0];
    const float* pred   = (const float*)d_in[1];
    const float* W_enc  = (const float*)d_in[2];
    const float* b_enc  = (const float*)d_in[3];
    const float* W_pred = (const float*)d_in[4];
    const float* b_pred = (const float*)d_in[5];
    const float* W_out  = (const float*)d_in[6];
    const float* b_out  = (const float*)d_in[7];
    float* out = (float*)d_out;

    cudaFuncSetAttribute(gemm_lm, cudaFuncAttributeMaxDynamicSharedMemorySize, DYN_SMEM);
    cudaFuncSetAttribute(proj_mma, cudaFuncAttributeMaxDynamicSharedMemorySize, PROJ_SMEM);

    convert_kernel<<<352, 256>>>(enc, pred, W_enc, W_pred, W_out);
    proj_mma<<<200, 128, PROJ_SMEM>>>(b_enc, b_pred);
    joint_tanh_kernel<<<(M_TOTAL * 80) / 256, 256>>>();
    gemm_lm<<<dim3(DV / BN, M_TOTAL / BM), 256, DYN_SMEM>>>(b_out, out);
}